// round 2
// baseline (speedup 1.0000x reference)
#include <cuda_runtime.h>

// ---------------------------------------------------------------------------
// HandGNNEncoder: 2-layer GCN over fixed 21-node skeleton + mean pool.
// Restructured:
//   y[t]   = (A_norm @ x)[t]                (sparse, <=3 nz/row, consts)
//   H[t,d] = relu(y[t,0]*W1[0,d] + y[t,1]*W1[1,d] + b1[d])
//   p[d]   = sum_t c[t] * H[t,d]            (c = column-mean of A_norm)
//   out    = p @ W2 + b2
// ---------------------------------------------------------------------------

#define R2  0.70710678118654752440f   // 1/sqrt(2)
#define R3  0.57735026918962576451f   // 1/sqrt(3)
#define TH  (1.0f/3.0f)
#define W23 (R2*R3)

// column sums of A_norm divided by 21 (mean-pool weights)
__device__ __constant__ float cPool[21] = {
    (1.0f + 2.0f*R2 + 3.0f*R3)/21.0f,
    1.0f/21.0f, 1.0f/21.0f, 1.0f/21.0f, 0.5f/21.0f,
    (1.0f + W23)/21.0f, 1.0f/21.0f, 1.0f/21.0f, 0.5f/21.0f,
    (2.0f/3.0f + W23)/21.0f, 1.0f/21.0f, 1.0f/21.0f, 0.5f/21.0f,
    (2.0f/3.0f + W23)/21.0f, 1.0f/21.0f, 1.0f/21.0f, 0.5f/21.0f,
    (1.0f/3.0f + W23)/21.0f, 1.0f/21.0f, 1.0f/21.0f, 0.5f/21.0f,
};

// sparse rows of A_norm: up to 3 (src, weight) entries per target node (0-pad)
__device__ __constant__ int cIdx[63] = {
    0,0,0,   1,0,0,   2,1,0,   3,2,0,   4,3,0,
    5,0,0,   6,5,0,   7,6,0,   8,7,0,
    9,0,5,   10,9,0,  11,10,0, 12,11,0,
    13,0,9,  14,13,0, 15,14,0, 16,15,0,
    17,0,13, 18,17,0, 19,18,0, 20,19,0
};
__device__ __constant__ float cWt[63] = {
    1.0f,0.f,0.f,   0.5f,R2,0.f,   0.5f,0.5f,0.f, 0.5f,0.5f,0.f, 0.5f,0.5f,0.f,
    0.5f,R2,0.f,    0.5f,0.5f,0.f, 0.5f,0.5f,0.f, 0.5f,0.5f,0.f,
    TH,R3,W23,      0.5f,W23,0.f,  0.5f,0.5f,0.f, 0.5f,0.5f,0.f,
    TH,R3,TH,       0.5f,W23,0.f,  0.5f,0.5f,0.f, 0.5f,0.5f,0.f,
    TH,R3,TH,       0.5f,W23,0.f,  0.5f,0.5f,0.f, 0.5f,0.5f,0.f
};

#define NWARP 8
#define THREADS 256
#define FULLMASK 0xffffffffu

__global__ __launch_bounds__(256)
void gnn_kernel(const float* __restrict__ x,
                const float* __restrict__ W1,
                const float* __restrict__ b1,
                const float* __restrict__ W2,
                const float* __restrict__ b2,
                float* __restrict__ out,
                int nquad, int G)
{
    __shared__ float4 W2s[64*32];            // 32 KB: W2 [64,128]
    __shared__ float2 ysh[NWARP][4][21];     // aggregated coords per warp/graph
    __shared__ float  psh[NWARP][4][64];     // pooled 64-vec per warp/graph
    __shared__ int    sIdx[63];
    __shared__ float  sWt[63];

    const int tid  = threadIdx.x;
    const int lane = tid & 31;
    const int warp = tid >> 5;

    // stage W2 into shared (row-major float4)
    for (int i = tid; i < 64*32; i += THREADS)
        W2s[i] = ((const float4*)W2)[i];
    if (tid < 63) { sIdx[tid] = cIdx[tid]; sWt[tid] = cWt[tid]; }

    // per-lane weight registers: lane owns D1 indices {lane, lane+32}
    const float w1a0 = W1[lane],      w1a1 = W1[64 + lane];
    const float w1b0 = W1[32 + lane], w1b1 = W1[96 + lane];
    const float b1a  = b1[lane],      b1b  = b1[32 + lane];
    const float4 b2v = ((const float4*)b2)[lane];

    __syncthreads();

    int s0 = 0, s1 = 0, s2 = 0;
    float aw0 = 0.f, aw1 = 0.f, aw2 = 0.f;
    if (lane < 21) {
        s0  = sIdx[lane*3];   s1  = sIdx[lane*3+1];   s2  = sIdx[lane*3+2];
        aw0 = sWt[lane*3];    aw1 = sWt[lane*3+1];    aw2 = sWt[lane*3+2];
    }

    const int wid  = blockIdx.x * NWARP + warp;
    const int totw = gridDim.x * NWARP;

    for (int q = wid; q < nquad; q += totw) {
        const int g0 = q * 4;

        // ---- load x: lane t < 21 holds (x,y) for node t, per graph j ----
        float2 xv[4];
        #pragma unroll
        for (int j = 0; j < 4; j++) {
            int g = g0 + j;
            xv[j] = (lane < 21 && g < G)
                    ? ((const float2*)x)[(size_t)g * 21 + lane]
                    : make_float2(0.f, 0.f);
        }

        // ---- stage 1: y = A_norm @ x via shuffles (weights are consts) ----
        #pragma unroll
        for (int j = 0; j < 4; j++) {
            float xs0x = __shfl_sync(FULLMASK, xv[j].x, s0);
            float xs0y = __shfl_sync(FULLMASK, xv[j].y, s0);
            float xs1x = __shfl_sync(FULLMASK, xv[j].x, s1);
            float xs1y = __shfl_sync(FULLMASK, xv[j].y, s1);
            float xs2x = __shfl_sync(FULLMASK, xv[j].x, s2);
            float xs2y = __shfl_sync(FULLMASK, xv[j].y, s2);
            if (lane < 21) {
                float yx = fmaf(aw2, xs2x, fmaf(aw1, xs1x, aw0 * xs0x));
                float yy = fmaf(aw2, xs2y, fmaf(aw1, xs1y, aw0 * xs0y));
                ysh[warp][j][lane] = make_float2(yx, yy);
            }
        }
        __syncwarp();

        // ---- stage 2: H = relu(y@W1 + b1); p = c^T H (pool) ----
        float pa[4], pb[4];
        #pragma unroll
        for (int j = 0; j < 4; j++) { pa[j] = 0.f; pb[j] = 0.f; }

        #pragma unroll
        for (int t = 0; t < 21; t++) {
            const float ct = cPool[t];
            #pragma unroll
            for (int j = 0; j < 4; j++) {
                const float2 yt = ysh[warp][j][t];
                float ha = fmaf(yt.x, w1a0, b1a);
                ha = fmaf(yt.y, w1a1, ha);
                ha = fmaxf(ha, 0.f);
                pa[j] = fmaf(ct, ha, pa[j]);
                float hb = fmaf(yt.x, w1b0, b1b);
                hb = fmaf(yt.y, w1b1, hb);
                hb = fmaxf(hb, 0.f);
                pb[j] = fmaf(ct, hb, pb[j]);
            }
        }
        #pragma unroll
        for (int j = 0; j < 4; j++) {
            psh[warp][j][lane]      = pa[j];
            psh[warp][j][lane + 32] = pb[j];
        }
        __syncwarp();

        // ---- stage 3: out = p @ W2 + b2 (lane owns 4 consecutive D2 cols) ----
        float4 acc[4];
        #pragma unroll
        for (int j = 0; j < 4; j++) acc[j] = b2v;

        #pragma unroll 16
        for (int k = 0; k < 64; k++) {
            const float4 w4 = W2s[k*32 + lane];
            #pragma unroll
            for (int j = 0; j < 4; j++) {
                const float pk = psh[warp][j][k];
                acc[j].x = fmaf(pk, w4.x, acc[j].x);
                acc[j].y = fmaf(pk, w4.y, acc[j].y);
                acc[j].z = fmaf(pk, w4.z, acc[j].z);
                acc[j].w = fmaf(pk, w4.w, acc[j].w);
            }
        }

        #pragma unroll
        for (int j = 0; j < 4; j++) {
            int g = g0 + j;
            if (g < G)
                ((float4*)out)[(size_t)g * 32 + lane] = acc[j];
        }
        __syncwarp();   // protect ysh/psh before next iteration rewrites
    }
}

extern "C" void kernel_launch(void* const* d_in, const int* in_sizes, int n_in,
                              void* d_out, int out_size) {
    const float* x  = (const float*)d_in[0];
    const float* W1 = (const float*)d_in[1];
    const float* b1 = (const float*)d_in[2];
    const float* W2 = (const float*)d_in[3];
    const float* b2 = (const float*)d_in[4];
    float* out = (float*)d_out;

    const int G = in_sizes[0] / 42;         // graphs = B*S
    const int nquad = (G + 3) / 4;

    gnn_kernel<<<592, THREADS>>>(x, W1, b1, W2, b2, out, nquad, G);
}